// round 15
// baseline (speedup 1.0000x reference)
#include <cuda_runtime.h>
#include <cuda_fp16.h>
#include <math.h>
#include <cstdint>

// ---------------------------------------------------------------------------
// Problem constants
// ---------------------------------------------------------------------------
static constexpr int BATCH = 2;
static constexpr int CDIM  = 256;
static constexpr int TSEQ  = 4096;   // 64*64
// 64^-0.25 * sqrt(log2(e)) : folds the exp->exp2 conversion into Q and K
static constexpr float QK_SCALE = 0.42466090936113257f;
static constexpr int NTILES = TSEQ / 64;  // 64 kv tiles of 64 keys
static constexpr int NSPLIT = 4;
static constexpr int SPT = NTILES / NSPLIT;  // 16 tiles per split

static constexpr int GEMM_SMEM = 3 * 24576;              // proj: 72 KB ring
static constexpr int QKV_SMEM  = 65536 + 24576 + 17408;  // A-resident: 105 KB

// Scratch (device globals; allocation-free)
__device__ __half g_xnh[BATCH * TSEQ * CDIM];  // GN out, [b][t][c] 4 MB
__device__ __half g_hh [BATCH * TSEQ * CDIM];  // attn out, [b][t][c] 4 MB
__device__ __half g_qh[8 * TSEQ * 64];         // [bh][t][c] 4 MB
__device__ __half g_kh[8 * TSEQ * 64];         // [bh][t][c] 4 MB
__device__ __half g_vh[8 * 64 * TSEQ];         // [bh][d][t] 4 MB
__device__ __half g_wqkvh[768 * 256];          // fp16 qkv weight
__device__ __half g_wprojh[256 * 256];         // fp16 proj weight
__device__ __half g_op[NSPLIT * 8 * TSEQ * 64]; // unnormalized O partials 16.8MB
__device__ float  g_lp[NSPLIT * 8 * TSEQ];      // l partials 512KB
__device__ float g_mean[64];
__device__ float g_rstd[64];

// ---------------------------------------------------------------------------
// PTX helpers (sm_80+ subset: mma.sync / ldmatrix / cp.async)
// ---------------------------------------------------------------------------
__device__ __forceinline__ uint32_t smem_to_u32(const void* p) {
    uint32_t a;
    asm("{ .reg .u64 t; cvta.to.shared.u64 t, %1; cvt.u32.u64 %0, t; }" : "=r"(a) : "l"(p));
    return a;
}

__device__ __forceinline__ void cp_async16(uint32_t saddr, const void* gaddr) {
    asm volatile("cp.async.cg.shared.global [%0], [%1], 16;" :: "r"(saddr), "l"(gaddr));
}
__device__ __forceinline__ void cp_commit() { asm volatile("cp.async.commit_group;"); }
template <int N>
__device__ __forceinline__ void cp_wait() { asm volatile("cp.async.wait_group %0;" :: "n"(N)); }

__device__ __forceinline__ void ldm_x4(uint32_t* r, uint32_t addr) {
    asm volatile("ldmatrix.sync.aligned.m8n8.x4.shared.b16 {%0,%1,%2,%3}, [%4];"
        : "=r"(r[0]), "=r"(r[1]), "=r"(r[2]), "=r"(r[3]) : "r"(addr));
}

__device__ __forceinline__ void mma_f16(float* c, const uint32_t* a, uint32_t b0, uint32_t b1) {
    asm volatile("mma.sync.aligned.m16n8k16.row.col.f32.f16.f16.f32 "
        "{%0,%1,%2,%3}, {%4,%5,%6,%7}, {%8,%9}, {%0,%1,%2,%3};"
        : "+f"(c[0]), "+f"(c[1]), "+f"(c[2]), "+f"(c[3])
        : "r"(a[0]), "r"(a[1]), "r"(a[2]), "r"(a[3]), "r"(b0), "r"(b1));
}

// f16 accumulator variant: D/C are 2 packed f16x2 regs.
__device__ __forceinline__ void mma_f16acc(uint32_t* c, const uint32_t* a, uint32_t b0, uint32_t b1) {
    asm volatile("mma.sync.aligned.m16n8k16.row.col.f16.f16.f16.f16 "
        "{%0,%1}, {%2,%3,%4,%5}, {%6,%7}, {%0,%1};"
        : "+r"(c[0]), "+r"(c[1])
        : "r"(a[0]), "r"(a[1]), "r"(a[2]), "r"(a[3]), "r"(b0), "r"(b1));
}

__device__ __forceinline__ uint32_t pack_f16x2(float lo, float hi) {
    uint32_t r;
    asm("cvt.rn.f16x2.f32 %0, %1, %2;" : "=r"(r) : "f"(hi), "f"(lo));
    return r;
}
__device__ __forceinline__ uint32_t ex2_f16x2(uint32_t a) {
    uint32_t r;
    asm("ex2.approx.f16x2 %0, %1;" : "=r"(r) : "r"(a));
    return r;
}
__device__ __forceinline__ uint32_t hadd2(uint32_t a, uint32_t b) {
    uint32_t r;
    asm("add.f16x2 %0, %1, %2;" : "=r"(r) : "r"(a), "r"(b));
    return r;
}

// ---------------------------------------------------------------------------
// GroupNorm stats + weight fp32->fp16 conversion (folded).
// ---------------------------------------------------------------------------
__global__ void gn_stats_kernel(const float* __restrict__ x,
                                const float* __restrict__ qkvw,
                                const float* __restrict__ projw) {
    int gtid = blockIdx.x * 256 + threadIdx.x;   // 0..16383
    #pragma unroll
    for (int p = 0; p < 6; p++) {
        int i = gtid + p * 16384;
        float2 v = *(const float2*)&qkvw[(size_t)i * 2];
        *(uint32_t*)&g_wqkvh[(size_t)i * 2] = pack_f16x2(v.x, v.y);
    }
    #pragma unroll
    for (int p = 0; p < 2; p++) {
        int i = gtid + p * 16384;
        float2 v = *(const float2*)&projw[(size_t)i * 2];
        *(uint32_t*)&g_wprojh[(size_t)i * 2] = pack_f16x2(v.x, v.y);
    }

    int bg = blockIdx.x;
    const float4* p = (const float4*)(x + (size_t)bg * 32768);
    float s = 0.f, s2 = 0.f;
    for (int i = threadIdx.x; i < 8192; i += 256) {
        float4 v = p[i];
        s  += v.x + v.y + v.z + v.w;
        s2 += v.x*v.x + v.y*v.y + v.z*v.z + v.w*v.w;
    }
    #pragma unroll
    for (int off = 16; off; off >>= 1) {
        s  += __shfl_xor_sync(0xffffffffu, s,  off);
        s2 += __shfl_xor_sync(0xffffffffu, s2, off);
    }
    __shared__ float as[8], bs[8];
    int w = threadIdx.x >> 5, lane = threadIdx.x & 31;
    if (lane == 0) { as[w] = s; bs[w] = s2; }
    __syncthreads();
    if (threadIdx.x == 0) {
        float ts = 0.f, t2 = 0.f;
        #pragma unroll
        for (int i = 0; i < 8; i++) { ts += as[i]; t2 += bs[i]; }
        float mu  = ts * (1.f / 32768.f);
        float var = t2 * (1.f / 32768.f) - mu * mu;
        g_mean[bg] = mu;
        g_rstd[bg] = rsqrtf(var + 1e-5f);
    }
}

// ---------------------------------------------------------------------------
// GroupNorm apply + transpose: x [b][c][t] fp32 -> g_xnh [b][t][c] fp16.
// ---------------------------------------------------------------------------
__global__ void gn_apply_t_kernel(const float* __restrict__ x,
                                  const float* __restrict__ w,
                                  const float* __restrict__ b) {
    __shared__ float tile[64][68];
    int b_ = blockIdx.z, c0 = blockIdx.x * 64, t0 = blockIdx.y * 64;

    #pragma unroll
    for (int p = 0; p < 4; p++) {
        int i = threadIdx.x + p * 256;
        int c = i >> 4, t4 = (i & 15) * 4;
        int cg = c0 + c;
        int bg = b_ * 32 + (cg >> 3);
        float sw = w[cg] * g_rstd[bg];
        float sb = b[cg] - g_mean[bg] * sw;
        float4 v = *(const float4*)&x[((size_t)(b_ * CDIM + cg)) * TSEQ + t0 + t4];
        tile[c][t4 + 0] = v.x * sw + sb;
        tile[c][t4 + 1] = v.y * sw + sb;
        tile[c][t4 + 2] = v.z * sw + sb;
        tile[c][t4 + 3] = v.w * sw + sb;
    }
    __syncthreads();

    #pragma unroll
    for (int p = 0; p < 8; p++) {
        int i = threadIdx.x + p * 256;
        int t = i >> 5, cp = (i & 31) * 2;
        uint32_t u = pack_f16x2(tile[cp][t], tile[cp + 1][t]);
        *(uint32_t*)&g_xnh[((size_t)(b_ * TSEQ + t0 + t)) * CDIM + c0 + cp] = u;
    }
}

// ---------------------------------------------------------------------------
// QKV GEMM, A-RESIDENT: block = (128-t tile, head). A tile [128t][256c]
// (64 KB, 4 chunks) loaded ONCE; B streams 12 tiles (3 o-tiles x 4 chunks)
// through a 3-stage 8 KB ring. Epilogues at j=3 (Q), 7 (K), 11 (V).
// ---------------------------------------------------------------------------
__global__ void __launch_bounds__(128)
gemm_qkv_h(const __half* __restrict__ Xt, const float* __restrict__ bias) {
    extern __shared__ __align__(128) char smg[];
    uint32_t sb = smem_to_u32(smg);
    const int tid = threadIdx.x, lane = tid & 31, wid = tid >> 5;
    int b_ = blockIdx.z, t0 = blockIdx.x * 128, head = blockIdx.y;
    int bh = b_ * 4 + head;

    const char* Ag = (const char*)(Xt + ((size_t)b_ * TSEQ + t0) * CDIM);
    const char* Bg = (const char*)(g_wqkvh + (size_t)head * 192 * CDIM);

    // A: 4 resident chunks of [128t][64c] SW128, chunk kc at sb + kc*16384.
    #pragma unroll
    for (int kc = 0; kc < 4; kc++) {
        #pragma unroll
        for (int p = 0; p < 8; p++) {
            int i = tid + p * 128;
            int row = i >> 3, c = i & 7;
            uint32_t soff = row * 128 + ((c ^ (row & 7)) * 16);
            cp_async16(sb + kc * 16384 + soff, Ag + (size_t)row * 512 + kc * 128 + c * 16);
        }
    }
    cp_commit();

    const uint32_t bB = sb + 65536;
    auto issueB = [&](int j) {
        int ot = j >> 2, kc = j & 3;
        uint32_t dst = bB + (uint32_t)(j % 3) * 8192;
        #pragma unroll
        for (int p = 0; p < 4; p++) {
            int i = tid + p * 128;
            int row = i >> 3, c = i & 7;
            uint32_t soff = row * 128 + ((c ^ (row & 7)) * 16);
            cp_async16(dst + soff, Bg + (size_t)(ot * 64 + row) * 512 + kc * 128 + c * 16);
        }
        cp_commit();
    };

    issueB(0);
    issueB(1);

    const int r0    = wid * 32 + (lane & 7) + (((lane >> 3) & 1) << 3);
    const int cbitA = lane >> 4;
    const int rowB  = (lane & 7) + ((lane >> 4) << 3);
    const int cbitB = (lane >> 3) & 1;
    const uint32_t brow = rowB * 128;

    const int q   = wid * 32 + (lane >> 2);
    const int cc2 = (lane & 3) * 2;

    float s0[8][4], s1[8][4];
    #pragma unroll
    for (int nt = 0; nt < 8; nt++)
        #pragma unroll
        for (int i2 = 0; i2 < 4; i2++) { s0[nt][i2] = 0.f; s1[nt][i2] = 0.f; }

    for (int j = 0; j < 12; j++) {
        if (j < 11) cp_wait<1>(); else cp_wait<0>();
        __syncthreads();                 // all warps done with B buffer (j-1)%3
        if (j + 2 < 12) issueB(j + 2);   // writes buffer (j+2)%3 == (j-1)%3

        int kc = j & 3;
        uint32_t abase = sb + (uint32_t)kc * 16384;
        uint32_t a0a = abase + r0 * 128;
        uint32_t a1a = abase + (r0 + 16) * 128;
        uint32_t kb  = bB + (uint32_t)(j % 3) * 8192 + brow;
        #pragma unroll
        for (int ks = 0; ks < 4; ks++) {
            uint32_t qa0[4], qa1[4];
            uint32_t co = (((ks * 2 + cbitA) ^ (r0 & 7)) << 4);
            ldm_x4(qa0, a0a + co);
            ldm_x4(qa1, a1a + co);
            uint32_t coffB = (((ks * 2 + cbitB) ^ (lane & 7)) << 4);
            #pragma unroll
            for (int nt2 = 0; nt2 < 4; nt2++) {
                uint32_t bfr[4];
                ldm_x4(bfr, kb + nt2 * 2048 + coffB);
                mma_f16(s0[nt2 * 2 + 0], qa0, bfr[0], bfr[1]);
                mma_f16(s0[nt2 * 2 + 1], qa0, bfr[2], bfr[3]);
                mma_f16(s1[nt2 * 2 + 0], qa1, bfr[0], bfr[1]);
                mma_f16(s1[nt2 * 2 + 1], qa1, bfr[2], bfr[3]);
            }
        }

        if ((j & 3) == 3) {
            int type = j >> 2;            // 0=Q 1=K 2=V
            int o0 = head * 192 + type * 64;
            if (type < 2) {
                // Direct-from-fragment stores; no smem, no extra sync.
                __half* dst = ((type == 0) ? g_qh : g_kh) + ((size_t)bh * TSEQ + t0) * 64;
                #pragma unroll
                for (int nt = 0; nt < 8; nt++) {
                    int ol = nt * 8 + cc2;
                    float b0 = bias[o0 + ol], b1 = bias[o0 + ol + 1];
                    *(uint32_t*)&dst[(size_t)q * 64 + ol] =
                        pack_f16x2((s0[nt][0] + b0) * QK_SCALE, (s0[nt][1] + b1) * QK_SCALE);
                    *(uint32_t*)&dst[(size_t)(q + 8) * 64 + ol] =
                        pack_f16x2((s0[nt][2] + b0) * QK_SCALE, (s0[nt][3] + b1) * QK_SCALE);
                    *(uint32_t*)&dst[(size_t)(q + 16) * 64 + ol] =
                        pack_f16x2((s1[nt][0] + b0) * QK_SCALE, (s1[nt][1] + b1) * QK_SCALE);
                    *(uint32_t*)&dst[(size_t)(q + 24) * 64 + ol] =
                        pack_f16x2((s1[nt][2] + b0) * QK_SCALE, (s1[nt][3] + b1) * QK_SCALE);
                }
            } else {
                // V: smem transpose via dedicated epi buffer.
                __half (*sv)[136] = (__half(*)[136])(smg + 65536 + 24576);
                #pragma unroll
                for (int nt = 0; nt < 8; nt++) {
                    int ol = nt * 8 + cc2;
                    float b0 = bias[o0 + ol], b1 = bias[o0 + ol + 1];
                    sv[ol][q]          = __float2half(s0[nt][0] + b0);
                    sv[ol + 1][q]      = __float2half(s0[nt][1] + b1);
                    sv[ol][q + 8]      = __float2half(s0[nt][2] + b0);
                    sv[ol + 1][q + 8]  = __float2half(s0[nt][3] + b1);
                    sv[ol][q + 16]     = __float2half(s1[nt][0] + b0);
                    sv[ol + 1][q + 16] = __float2half(s1[nt][1] + b1);
                    sv[ol][q + 24]     = __float2half(s1[nt][2] + b0);
                    sv[ol + 1][q + 24] = __float2half(s1[nt][3] + b1);
                }
                __syncthreads();
                for (int i = tid; i < 4096; i += 128) {
                    int d = i >> 6, tp = (i & 63) * 2;
                    uint32_t u = pack_f16x2(__half2float(sv[d][tp]), __half2float(sv[d][tp + 1]));
                    *(uint32_t*)&g_vh[((size_t)bh * 64 + d) * TSEQ + t0 + tp] = u;
                }
            }
            if (type < 2) {
                #pragma unroll
                for (int nt = 0; nt < 8; nt++)
                    #pragma unroll
                    for (int i2 = 0; i2 < 4; i2++) { s0[nt][i2] = 0.f; s1[nt][i2] = 0.f; }
            }
        }
    }
}

// ---------------------------------------------------------------------------
// Proj GEMM mainloop (R14 3-stage ring) + bias + residual, fp32 out [b][o][t].
// ---------------------------------------------------------------------------
__device__ __forceinline__ void gemm_mainloop2(
    uint32_t sb, const char* Ag, const char* Bg,
    float (*s0)[4], float (*s1)[4]) {
    const int tid = threadIdx.x, lane = tid & 31, wid = tid >> 5;
    const int r0    = wid * 32 + (lane & 7) + (((lane >> 3) & 1) << 3);
    const int cbitA = lane >> 4;
    const int rowB  = (lane & 7) + ((lane >> 4) << 3);
    const int cbitB = (lane >> 3) & 1;
    const uint32_t brow = rowB * 128;

    #pragma unroll
    for (int nt = 0; nt < 8; nt++)
        #pragma unroll
        for (int i = 0; i < 4; i++) { s0[nt][i] = 0.f; s1[nt][i] = 0.f; }

    auto issue = [&](int kc) {
        uint32_t dst = sb + (uint32_t)(kc % 3) * 24576;
        #pragma unroll
        for (int p = 0; p < 8; p++) {
            int i = tid + p * 128;
            int row = i >> 3, c = i & 7;
            uint32_t soff = row * 128 + ((c ^ (row & 7)) * 16);
            cp_async16(dst + soff, Ag + (size_t)row * 512 + kc * 128 + c * 16);
        }
        #pragma unroll
        for (int p = 0; p < 4; p++) {
            int i = tid + p * 128;
            int row = i >> 3, c = i & 7;
            uint32_t soff = row * 128 + ((c ^ (row & 7)) * 16);
            cp_async16(dst + 16384 + soff, Bg + (size_t)row * 512 + kc * 128 + c * 16);
        }
        cp_commit();
    };

    issue(0);
    issue(1);
    #pragma unroll
    for (int kc = 0; kc < 4; kc++) {
        if (kc < 3) cp_wait<1>(); else cp_wait<0>();
        __syncthreads();
        if (kc + 2 < 4) issue(kc + 2);
        uint32_t abase = sb + (uint32_t)(kc % 3) * 24576;
        uint32_t a0 = abase + r0 * 128;
        uint32_t a1 = abase + (r0 + 16) * 128;
        uint32_t kbase = abase + 16384 + brow;
        #pragma unroll
        for (int ks = 0; ks < 4; ks++) {
            uint32_t qa0[4], qa1[4];
            uint32_t co = (((ks * 2 + cbitA) ^ (r0 & 7)) << 4);
            ldm_x4(qa0, a0 + co);
            ldm_x4(qa1, a1 + co);
            uint32_t coffB = (((ks * 2 + cbitB) ^ (lane & 7)) << 4);
            #pragma unroll
            for (int nt2 = 0; nt2 < 4; nt2++) {
                uint32_t bfr[4];
                ldm_x4(bfr, kbase + nt2 * 2048 + coffB);
                mma_f16(s0[nt2 * 2 + 0], qa0, bfr[0], bfr[1]);
                mma_f16(s0[nt2 * 2 + 1], qa0, bfr[2], bfr[3]);
                mma_f16(s1[nt2 * 2 + 0], qa1, bfr[0], bfr[1]);
                mma_f16(s1[nt2 * 2 + 1], qa1, bfr[2], bfr[3]);
            }
        }
    }
    __syncthreads();
}

__global__ void __launch_bounds__(128)
gemm_proj_h(const __half* __restrict__ Ht, const float* __restrict__ bias,
            const float* __restrict__ R, float* __restrict__ Y) {
    extern __shared__ __align__(128) char smg[];
    uint32_t sb = smem_to_u32(smg);
    int b_ = blockIdx.z, t0 = blockIdx.x * 128, o0 = blockIdx.y * 64;

    float s0[8][4], s1[8][4];
    gemm_mainloop2(sb,
        (const char*)(Ht + ((size_t)b_ * TSEQ + t0) * CDIM),
        (const char*)(g_wprojh + (size_t)o0 * CDIM), s0, s1);

    const int lane = threadIdx.x & 31, wid = threadIdx.x >> 5;
    int q   = wid * 32 + (lane >> 2);
    int cc2 = (lane & 3) * 2;

    float (*so)[132] = (float(*)[132])smg;   // [64 o][128 t + pad]
    #pragma unroll
    for (int nt = 0; nt < 8; nt++) {
        int ol = nt * 8 + cc2;
        so[ol][q]          = s0[nt][0];
        so[ol + 1][q]      = s0[nt][1];
        so[ol][q + 8]      = s0[nt][2];
        so[ol + 1][q + 8]  = s0[nt][3];
        so[ol][q + 16]     = s1[nt][0];
        so[ol + 1][q + 16] = s1[nt][1];
        so[ol][q + 24]     = s1[nt][2];
        so[ol + 1][q + 24] = s1[nt][3];
    }
    __syncthreads();
    for (int i = threadIdx.x; i < 2048; i += 128) {
        int o = i >> 5, t4 = (i & 31) * 4;
        size_t idx = ((size_t)(b_ * CDIM + o0 + o)) * TSEQ + t0 + t4;
        float4 rv = *(const float4*)&R[idx];
        float bvv = bias[o0 + o];
        float4 r;
        r.x = so[o][t4 + 0] + bvv + rv.x;
        r.y = so[o][t4 + 1] + bvv + rv.y;
        r.z = so[o][t4 + 2] + bvv + rv.z;
        r.w = so[o][t4 + 3] + bvv + rv.w;
        *(float4*)&Y[idx] = r;
    }
}

// ---------------------------------------------------------------------------
// Flash attention, fp16 mma.sync, SPLIT-KV x4 (unchanged from R13).
// ---------------------------------------------------------------------------
__global__ void __launch_bounds__(128, 2)
attn_mma_kernel(const __half* __restrict__ Qh,
                const __half* __restrict__ Kh,
                const __half* __restrict__ Vh) {
    __shared__ __align__(128) char smem[49152];   // 3 stages x 16 KB
    uint32_t sb = smem_to_u32(smem);
    const int tid = threadIdx.x, lane = tid & 31, wid = tid >> 5;
    const int bh = blockIdx.y, q0 = blockIdx.x * 128, sp = blockIdx.z;
    const int base = sp * SPT;

    const char* Kg = (const char*)(Kh + (size_t)bh * TSEQ * 64);
    const char* Vg = (const char*)(Vh + (size_t)bh * 64 * TSEQ);

    {
        const char* Qg = (const char*)(Qh + ((size_t)bh * TSEQ + q0) * 64);
        #pragma unroll
        for (int p = 0; p < 8; p++) {
            int i = tid + p * 128;
            int row = i >> 3, c = i & 7;
            cp_async16(sb + row * 128 + ((c ^ (row & 7)) * 16), Qg + row * 128 + c * 16);
        }
        cp_commit();
        cp_wait<0>();
        __syncthreads();
    }
    uint32_t qa0[4][4], qa1[4][4];
    {
        int r0 = wid * 32 + (lane & 7) + (((lane >> 3) & 1) << 3);
        int cbit = lane >> 4;
        uint32_t b0 = sb + r0 * 128;
        uint32_t b1 = sb + (r0 + 16) * 128;
        #pragma unroll
        for (int ks = 0; ks < 4; ks++) {
            uint32_t co = (((ks * 2 + cbit) ^ (r0 & 7)) << 4);
            ldm_x4(qa0[ks], b0 + co);
            ldm_x4(qa1[ks], b1 + co);
        }
    }
    __syncthreads();

    const int rowB  = (lane & 7) + ((lane >> 4) << 3);
    const int cbitB = (lane >> 3) & 1;
    const uint32_t browoff = rowB * 128;

    float o0[8][4], o1[8][4];
    #pragma unroll
    for (int nt = 0; nt < 8; nt++)
        #pragma unroll
        for (int i = 0; i < 4; i++) { o0[nt][i] = 0.f; o1[nt][i] = 0.f; }
    float l0 = 0.f, l1 = 0.f, l2 = 0.f, l3 = 0.f;

    auto issue = [&](int ii) {
        uint32_t dst = sb + (uint32_t)(ii % 3) * 16384;
        int it = base + ii;
        const char* kg = Kg + (size_t)it * 64 * 128;
        #pragma unroll
        for (int p = 0; p < 4; p++) {
            int i = tid + p * 128;
            int row = i >> 3, c = i & 7;
            uint32_t soff = row * 128 + ((c ^ (row & 7)) * 16);
            cp_async16(dst + soff, kg + row * 128 + c * 16);
            cp_async16(dst + 8192 + soff, Vg + (size_t)row * 8192 + (size_t)it * 128 + c * 16);
        }
        cp_commit();
    };

    issue(0);
    issue(1);

    for (int ii = 0; ii < SPT; ii++) {
        if (ii < SPT - 1) cp_wait<1>(); else cp_wait<0>();
        __syncthreads();
        if (ii + 2 < SPT) issue(ii + 2);

        uint32_t kbase = sb + (uint32_t)(ii % 3) * 16384 + browoff;
        uint32_t vbase = kbase + 8192;

        uint32_t sh0[8][2], sh1[8][2];
        #pragma unroll
        for (int nt = 0; nt < 8; nt++) {
            sh0[nt][0] = 0u; sh0[nt][1] = 0u;
            sh1[nt][0] = 0u; sh1[nt][1] = 0u;
        }

        #pragma unroll
        for (int ks = 0; ks < 4; ks++) {
            uint32_t coff = (((ks * 2 + cbitB) ^ (lane & 7)) << 4);
            #pragma unroll
            for (int nt2 = 0; nt2 < 4; nt2++) {
                uint32_t bfr[4];
                ldm_x4(bfr, kbase + nt2 * 2048 + coff);
                mma_f16acc(sh0[nt2 * 2 + 0], qa0[ks], bfr[0], bfr[1]);
                mma_f16acc(sh0[nt2 * 2 + 1], qa0[ks], bfr[2], bfr[3]);
                mma_f16acc(sh1[nt2 * 2 + 0], qa1[ks], bfr[0], bfr[1]);
                mma_f16acc(sh1[nt2 * 2 + 1], qa1[ks], bfr[2], bfr[3]);
            }
        }

        uint32_t pa0[4][4], pa1[4][4];
        #pragma unroll
        for (int jt = 0; jt < 4; jt++) {
            pa0[jt][0] = ex2_f16x2(sh0[2*jt][0]);
            pa0[jt][1] = ex2_f16x2(sh0[2*jt][1]);
            pa0[jt][2] = ex2_f16x2(sh0[2*jt+1][0]);
            pa0[jt][3] = ex2_f16x2(sh0[2*jt+1][1]);
            pa1[jt][0] = ex2_f16x2(sh1[2*jt][0]);
            pa1[jt][1] = ex2_f16x2(sh1[2*jt][1]);
            pa1[jt][2] = ex2_f16x2(sh1[2*jt+1][0]);
            pa1[jt][3] = ex2_f16x2(sh1[2*jt+1][1]);
        }
        {
            uint32_t a0 = hadd2(hadd2(pa0[0][0], pa0[1][0]), hadd2(pa0[2][0], pa0[3][0]));
            uint32_t a0b = hadd2(hadd2(pa0[0][2], pa0[1][2]), hadd2(pa0[2][2], pa0[3][2]));
            uint32_t a1 = hadd2(hadd2(pa0[0][1], pa0[1][1]), hadd2(pa0[2][1], pa0[3][1]));
            uint32_t a1b = hadd2(hadd2(pa0[0][3], pa0[1][3]), hadd2(pa0[2][3], pa0[3][3]));
            __half2 h0 = __hadd2(*(__half2*)&a0, *(__half2*)&a0b);
            __half2 h1 = __hadd2(*(__half2*)&a1, *(__half2*)&a1b);
            l0 += __low2float(h0) + __high2float(h0);
            l1 += __low2float(h1) + __high2float(h1);
            uint32_t c0 = hadd2(hadd2(pa1[0][0], pa1[1][0]), hadd2(pa1[2][0], pa1[3][0]));
            uint32_t c0b = hadd2(hadd2(pa1[0][2], pa1[1][2]), hadd2(pa1[2][2], pa1[3][2]));
            uint32_t c1 = hadd2(hadd2(pa1[0][1], pa1[1][1]), hadd2(pa1[2][1], pa1[3][1]));
            uint32_t c1b = hadd2(hadd2(pa1[0][3], pa1[1][3]), hadd2(pa1[2][3], pa1[3][3]));
            __half2 h2 = __hadd2(*(__half2*)&c0, *(__half2*)&c0b);
            __half2 h3 = __hadd2(*(__half2*)&c1, *(__half2*)&c1b);
            l2 += __low2float(h2) + __high2float(h2);
            l3 += __low2float(h3) + __high2float(h3);
        }

        #pragma unroll
        for (int jt = 0; jt < 4; jt++) {
            uint32_t coff = (((jt * 2 + cbitB) ^ (lane & 7)) << 4);
            #pragma unroll
            for (int nt2 = 0; nt2 < 4; nt2++) {
                uint32_t bfr[4];
                ldm_x4(bfr, vbase + nt2 * 2048 + coff);
                mma_f16(o0[nt2 * 2 + 0], pa0[jt], bfr[0], bfr[1]);
                mma_f16(o0[nt2 * 2 + 1], pa0[jt], bfr[2], bfr[3]);
                mma_f16(o1[nt2 * 2 + 0], pa1[jt], bfr[0], bfr[1]);
                mma_f16(o1[nt2 * 2 + 1], pa1[jt], bfr[2], bfr[3]);
            }
        }
    }

    #pragma unroll
    for (int off = 1; off <= 2; off <<= 1) {
        l0 += __shfl_xor_sync(0xffffffffu, l0, off);
        l1 += __shfl_xor_sync(0xffffffffu, l1, off);
        l2 += __shfl_xor_sync(0xffffffffu, l2, off);
        l3 += __shfl_xor_sync(0xffffffffu, l3, off);
    }

    int q  = wid * 32 + (lane >> 2);
    int cc = (lane & 3) * 2;
    __half* op = g_op + ((size_t)(sp * 8 + bh) * TSEQ + q0) * 64;
    #pragma unroll
    for (int nt = 0; nt < 8; nt++) {
        int d0 = nt * 8 + cc;
        *(uint32_t*)&op[(size_t)q * 64 + d0]        = pack_f16x2(o0[nt][0], o0[nt][1]);
        *(uint32_t*)&op[(size_t)(q + 8) * 64 + d0]  = pack_f16x2(o0[nt][2], o0[nt][3]);
        *(uint32_t*)&op[(size_t)(q + 16) * 64 + d0] = pack_f16x2(o1[nt][0], o1[nt][1]);
        *(uint32_t*)&op[(size_t)(q + 24) * 64 + d0] = pack_f16x2(o1[nt][2], o1[nt][3]);
    }
    if ((lane & 3) == 0) {
        float* lp = g_lp + (size_t)(sp * 8 + bh) * TSEQ + q0;
        lp[q] = l0; lp[q + 8] = l1; lp[q + 16] = l2; lp[q + 24] = l3;
    }
}

// ---------------------------------------------------------------------------
// Split-KV combine: h[row][d] = (sum_s O_s) / (sum_s l_s), emit hT fp16.
// ---------------------------------------------------------------------------
__global__ void attn_combine_kernel() {
    int gid = blockIdx.x * 256 + threadIdx.x;   // 524288
    int row = gid >> 4;
    int d4  = (gid & 15) * 4;

    float l = g_lp[row] + g_lp[32768 + row] + g_lp[65536 + row] + g_lp[98304 + row];
    float inv = 1.f / l;

    float a0 = 0.f, a1 = 0.f, a2 = 0.f, a3 = 0.f;
    #pragma unroll
    for (int s = 0; s < NSPLIT; s++) {
        uint2 u = *(const uint2*)&g_op[((size_t)s * 8 * TSEQ + row) * 64 + d4];
        __half2 x = *(__half2*)&u.x, y = *(__half2*)&u.y;
        a0 += __low2float(x); a1 += __high2float(x);
        a2 += __low2float(y); a3 += __high2float(y);
    }
    int bh = row >> 12, t = row & 4095;
    uint2 o;
    o.x = pack_f16x2(a0 * inv, a1 * inv);
    o.y = pack_f16x2(a2 * inv, a3 * inv);
    *(uint2*)&g_hh[((size_t)(bh >> 2) * TSEQ + t) * CDIM + (bh & 3) * 64 + d4] = o;
}

// ---------------------------------------------------------------------------
// Launch
// ---------------------------------------------------------------------------
extern "C" void kernel_launch(void* const* d_in, const int* in_sizes, int n_in,
                              void* d_out, int out_size) {
    const float* x      = (const float*)d_in[0];
    const float* gn_w   = (const float*)d_in[1];
    const float* gn_b   = (const float*)d_in[2];
    const float* qkv_w  = (const float*)d_in[3];
    const float* qkv_b  = (const float*)d_in[4];
    const float* proj_w = (const float*)d_in[5];
    const float* proj_b = (const float*)d_in[6];
    float* out = (float*)d_out;

    __half *xnh, *hh, *qh, *kh, *vh;
    cudaGetSymbolAddress((void**)&xnh, g_xnh);
    cudaGetSymbolAddress((void**)&hh,  g_hh);
    cudaGetSymbolAddress((void**)&qh,  g_qh);
    cudaGetSymbolAddress((void**)&kh,  g_kh);
    cudaGetSymbolAddress((void**)&vh,  g_vh);

    cudaFuncSetAttribute(gemm_qkv_h,
                         cudaFuncAttributeMaxDynamicSharedMemorySize, QKV_SMEM);
    cudaFuncSetAttribute(gemm_proj_h,
                         cudaFuncAttributeMaxDynamicSharedMemorySize, GEMM_SMEM);

    gn_stats_kernel<<<64, 256>>>(x, qkv_w, proj_w);
    gn_apply_t_kernel<<<dim3(4, 64, 2), 256>>>(x, gn_w, gn_b);
    gemm_qkv_h<<<dim3(32, 4, 2), 128, QKV_SMEM>>>(xnh, qkv_b);
    attn_mma_kernel<<<dim3(32, 8, NSPLIT), 128>>>(qh, kh, vh);
    attn_combine_kernel<<<2048, 256>>>();
    gemm_proj_h<<<dim3(32, 4, 2), 128, GEMM_SMEM>>>(hh, proj_b, x, out);
}

// round 16
// speedup vs baseline: 1.0121x; 1.0121x over previous
#include <cuda_runtime.h>
#include <cuda_fp16.h>
#include <math.h>
#include <cstdint>

// ---------------------------------------------------------------------------
// Problem constants
// ---------------------------------------------------------------------------
static constexpr int BATCH = 2;
static constexpr int CDIM  = 256;
static constexpr int TSEQ  = 4096;   // 64*64
// 64^-0.25 * sqrt(log2(e)) : folds the exp->exp2 conversion into Q and K
static constexpr float QK_SCALE = 0.42466090936113257f;
static constexpr int NTILES = TSEQ / 64;  // 64 kv tiles of 64 keys
static constexpr int NSPLIT = 4;
static constexpr int SPT = NTILES / NSPLIT;  // 16 tiles per split

static constexpr int GEMM_SMEM = 3 * 24576;      // GEMMs: 72 KB 3-stage ring
static constexpr int ATT_SMEM  = 16384 + 49152;  // attn: Q 16KB + 3x16KB stages

// Scratch (device globals; allocation-free)
__device__ __half g_xnh[BATCH * TSEQ * CDIM];  // GN out, [b][t][c] 4 MB
__device__ __half g_hh [BATCH * TSEQ * CDIM];  // attn out, [b][t][c] 4 MB
__device__ __half g_qh[8 * TSEQ * 64];         // [bh][t][c] 4 MB
__device__ __half g_kh[8 * TSEQ * 64];         // [bh][t][c] 4 MB
__device__ __half g_vh[8 * 64 * TSEQ];         // [bh][d][t] 4 MB
__device__ __half g_wqkvh[768 * 256];          // fp16 qkv weight
__device__ __half g_wprojh[256 * 256];         // fp16 proj weight
__device__ __half g_op[NSPLIT * 8 * TSEQ * 64]; // unnormalized O partials 16.8MB
__device__ float  g_lp[NSPLIT * 8 * TSEQ];      // l partials 512KB
__device__ float g_mean[64];
__device__ float g_rstd[64];

// ---------------------------------------------------------------------------
// PTX helpers (sm_80+ subset: mma.sync / ldmatrix / cp.async)
// ---------------------------------------------------------------------------
__device__ __forceinline__ uint32_t smem_to_u32(const void* p) {
    uint32_t a;
    asm("{ .reg .u64 t; cvta.to.shared.u64 t, %1; cvt.u32.u64 %0, t; }" : "=r"(a) : "l"(p));
    return a;
}

__device__ __forceinline__ void cp_async16(uint32_t saddr, const void* gaddr) {
    asm volatile("cp.async.cg.shared.global [%0], [%1], 16;" :: "r"(saddr), "l"(gaddr));
}
__device__ __forceinline__ void cp_commit() { asm volatile("cp.async.commit_group;"); }
template <int N>
__device__ __forceinline__ void cp_wait() { asm volatile("cp.async.wait_group %0;" :: "n"(N)); }

__device__ __forceinline__ void ldm_x4(uint32_t* r, uint32_t addr) {
    asm volatile("ldmatrix.sync.aligned.m8n8.x4.shared.b16 {%0,%1,%2,%3}, [%4];"
        : "=r"(r[0]), "=r"(r[1]), "=r"(r[2]), "=r"(r[3]) : "r"(addr));
}

__device__ __forceinline__ void mma_f16(float* c, const uint32_t* a, uint32_t b0, uint32_t b1) {
    asm volatile("mma.sync.aligned.m16n8k16.row.col.f32.f16.f16.f32 "
        "{%0,%1,%2,%3}, {%4,%5,%6,%7}, {%8,%9}, {%0,%1,%2,%3};"
        : "+f"(c[0]), "+f"(c[1]), "+f"(c[2]), "+f"(c[3])
        : "r"(a[0]), "r"(a[1]), "r"(a[2]), "r"(a[3]), "r"(b0), "r"(b1));
}

// f16 accumulator variant: D/C are 2 packed f16x2 regs.
__device__ __forceinline__ void mma_f16acc(uint32_t* c, const uint32_t* a, uint32_t b0, uint32_t b1) {
    asm volatile("mma.sync.aligned.m16n8k16.row.col.f16.f16.f16.f16 "
        "{%0,%1}, {%2,%3,%4,%5}, {%6,%7}, {%0,%1};"
        : "+r"(c[0]), "+r"(c[1])
        : "r"(a[0]), "r"(a[1]), "r"(a[2]), "r"(a[3]), "r"(b0), "r"(b1));
}

__device__ __forceinline__ uint32_t pack_f16x2(float lo, float hi) {
    uint32_t r;
    asm("cvt.rn.f16x2.f32 %0, %1, %2;" : "=r"(r) : "f"(hi), "f"(lo));
    return r;
}
__device__ __forceinline__ uint32_t ex2_f16x2(uint32_t a) {
    uint32_t r;
    asm("ex2.approx.f16x2 %0, %1;" : "=r"(r) : "r"(a));
    return r;
}
__device__ __forceinline__ uint32_t hadd2(uint32_t a, uint32_t b) {
    uint32_t r;
    asm("add.f16x2 %0, %1, %2;" : "=r"(r) : "r"(a), "r"(b));
    return r;
}

// ---------------------------------------------------------------------------
// GroupNorm stats + weight fp32->fp16 conversion (folded).
// ---------------------------------------------------------------------------
__global__ void gn_stats_kernel(const float* __restrict__ x,
                                const float* __restrict__ qkvw,
                                const float* __restrict__ projw) {
    int gtid = blockIdx.x * 256 + threadIdx.x;   // 0..16383
    #pragma unroll
    for (int p = 0; p < 6; p++) {
        int i = gtid + p * 16384;
        float2 v = *(const float2*)&qkvw[(size_t)i * 2];
        *(uint32_t*)&g_wqkvh[(size_t)i * 2] = pack_f16x2(v.x, v.y);
    }
    #pragma unroll
    for (int p = 0; p < 2; p++) {
        int i = gtid + p * 16384;
        float2 v = *(const float2*)&projw[(size_t)i * 2];
        *(uint32_t*)&g_wprojh[(size_t)i * 2] = pack_f16x2(v.x, v.y);
    }

    int bg = blockIdx.x;
    const float4* p = (const float4*)(x + (size_t)bg * 32768);
    float s = 0.f, s2 = 0.f;
    for (int i = threadIdx.x; i < 8192; i += 256) {
        float4 v = p[i];
        s  += v.x + v.y + v.z + v.w;
        s2 += v.x*v.x + v.y*v.y + v.z*v.z + v.w*v.w;
    }
    #pragma unroll
    for (int off = 16; off; off >>= 1) {
        s  += __shfl_xor_sync(0xffffffffu, s,  off);
        s2 += __shfl_xor_sync(0xffffffffu, s2, off);
    }
    __shared__ float as[8], bs[8];
    int w = threadIdx.x >> 5, lane = threadIdx.x & 31;
    if (lane == 0) { as[w] = s; bs[w] = s2; }
    __syncthreads();
    if (threadIdx.x == 0) {
        float ts = 0.f, t2 = 0.f;
        #pragma unroll
        for (int i = 0; i < 8; i++) { ts += as[i]; t2 += bs[i]; }
        float mu  = ts * (1.f / 32768.f);
        float var = t2 * (1.f / 32768.f) - mu * mu;
        g_mean[bg] = mu;
        g_rstd[bg] = rsqrtf(var + 1e-5f);
    }
}

// ---------------------------------------------------------------------------
// GroupNorm apply + transpose: x [b][c][t] fp32 -> g_xnh [b][t][c] fp16.
// ---------------------------------------------------------------------------
__global__ void gn_apply_t_kernel(const float* __restrict__ x,
                                  const float* __restrict__ w,
                                  const float* __restrict__ b) {
    __shared__ float tile[64][68];
    int b_ = blockIdx.z, c0 = blockIdx.x * 64, t0 = blockIdx.y * 64;

    #pragma unroll
    for (int p = 0; p < 4; p++) {
        int i = threadIdx.x + p * 256;
        int c = i >> 4, t4 = (i & 15) * 4;
        int cg = c0 + c;
        int bg = b_ * 32 + (cg >> 3);
        float sw = w[cg] * g_rstd[bg];
        float sb = b[cg] - g_mean[bg] * sw;
        float4 v = *(const float4*)&x[((size_t)(b_ * CDIM + cg)) * TSEQ + t0 + t4];
        tile[c][t4 + 0] = v.x * sw + sb;
        tile[c][t4 + 1] = v.y * sw + sb;
        tile[c][t4 + 2] = v.z * sw + sb;
        tile[c][t4 + 3] = v.w * sw + sb;
    }
    __syncthreads();

    #pragma unroll
    for (int p = 0; p < 8; p++) {
        int i = threadIdx.x + p * 256;
        int t = i >> 5, cp = (i & 31) * 2;
        uint32_t u = pack_f16x2(tile[cp][t], tile[cp + 1][t]);
        *(uint32_t*)&g_xnh[((size_t)(b_ * TSEQ + t0 + t)) * CDIM + c0 + cp] = u;
    }
}

// ---------------------------------------------------------------------------
// Shared fp16 TN GEMM mainloop, 128(t) x 64(o) tile, 4 warps x 32 t-rows.
// 3-stage cp.async ring (24KB stages), one sync per K-chunk.
// ---------------------------------------------------------------------------
__device__ __forceinline__ void gemm_mainloop2(
    uint32_t sb, const char* Ag, const char* Bg,
    float (*s0)[4], float (*s1)[4]) {
    const int tid = threadIdx.x, lane = tid & 31, wid = tid >> 5;
    const int r0    = wid * 32 + (lane & 7) + (((lane >> 3) & 1) << 3);
    const int cbitA = lane >> 4;
    const int rowB  = (lane & 7) + ((lane >> 4) << 3);
    const int cbitB = (lane >> 3) & 1;
    const uint32_t brow = rowB * 128;

    #pragma unroll
    for (int nt = 0; nt < 8; nt++)
        #pragma unroll
        for (int i = 0; i < 4; i++) { s0[nt][i] = 0.f; s1[nt][i] = 0.f; }

    auto issue = [&](int kc) {
        uint32_t dst = sb + (uint32_t)(kc % 3) * 24576;
        #pragma unroll
        for (int p = 0; p < 8; p++) {
            int i = tid + p * 128;
            int row = i >> 3, c = i & 7;
            uint32_t soff = row * 128 + ((c ^ (row & 7)) * 16);
            cp_async16(dst + soff, Ag + (size_t)row * 512 + kc * 128 + c * 16);
        }
        #pragma unroll
        for (int p = 0; p < 4; p++) {
            int i = tid + p * 128;
            int row = i >> 3, c = i & 7;
            uint32_t soff = row * 128 + ((c ^ (row & 7)) * 16);
            cp_async16(dst + 16384 + soff, Bg + (size_t)row * 512 + kc * 128 + c * 16);
        }
        cp_commit();
    };

    issue(0);
    issue(1);
    #pragma unroll
    for (int kc = 0; kc < 4; kc++) {
        if (kc < 3) cp_wait<1>(); else cp_wait<0>();
        __syncthreads();
        if (kc + 2 < 4) issue(kc + 2);
        uint32_t abase = sb + (uint32_t)(kc % 3) * 24576;
        uint32_t a0 = abase + r0 * 128;
        uint32_t a1 = abase + (r0 + 16) * 128;
        uint32_t kbase = abase + 16384 + brow;
        #pragma unroll
        for (int ks = 0; ks < 4; ks++) {
            uint32_t qa0[4], qa1[4];
            uint32_t co = (((ks * 2 + cbitA) ^ (r0 & 7)) << 4);
            ldm_x4(qa0, a0 + co);
            ldm_x4(qa1, a1 + co);
            uint32_t coffB = (((ks * 2 + cbitB) ^ (lane & 7)) << 4);
            #pragma unroll
            for (int nt2 = 0; nt2 < 4; nt2++) {
                uint32_t bfr[4];
                ldm_x4(bfr, kbase + nt2 * 2048 + coffB);
                mma_f16(s0[nt2 * 2 + 0], qa0, bfr[0], bfr[1]);
                mma_f16(s0[nt2 * 2 + 1], qa0, bfr[2], bfr[3]);
                mma_f16(s1[nt2 * 2 + 0], qa1, bfr[0], bfr[1]);
                mma_f16(s1[nt2 * 2 + 1], qa1, bfr[2], bfr[3]);
            }
        }
    }
    __syncthreads();   // before epilogue reuses smem
}

// ---------------------------------------------------------------------------
// QKV GEMM: 128t x 64o tiles. Epilogue routes to Q/K [bh][t][c] (scaled)
// directly from fragments, or V [bh][d][t] via smem transpose.
// ---------------------------------------------------------------------------
__global__ void __launch_bounds__(128)
gemm_qkv_h(const __half* __restrict__ Xt, const float* __restrict__ bias) {
    extern __shared__ __align__(128) char smg[];
    uint32_t sb = smem_to_u32(smg);
    int b_ = blockIdx.z, t0 = blockIdx.x * 128, o0 = blockIdx.y * 64;

    float s0[8][4], s1[8][4];
    gemm_mainloop2(sb,
        (const char*)(Xt + ((size_t)b_ * TSEQ + t0) * CDIM),
        (const char*)(g_wqkvh + (size_t)o0 * CDIM), s0, s1);

    const int lane = threadIdx.x & 31, wid = threadIdx.x >> 5;
    int q   = wid * 32 + (lane >> 2);
    int cc2 = (lane & 3) * 2;

    int h    = o0 / 192;
    int type = (o0 % 192) / 64;   // 0=Q 1=K 2=V
    int bh   = b_ * 4 + h;

    if (type < 2) {
        __half* dst = ((type == 0) ? g_qh : g_kh) + ((size_t)bh * TSEQ + t0) * 64;
        #pragma unroll
        for (int nt = 0; nt < 8; nt++) {
            int ol = nt * 8 + cc2;
            float b0 = bias[o0 + ol], b1 = bias[o0 + ol + 1];
            *(uint32_t*)&dst[(size_t)q * 64 + ol] =
                pack_f16x2((s0[nt][0] + b0) * QK_SCALE, (s0[nt][1] + b1) * QK_SCALE);
            *(uint32_t*)&dst[(size_t)(q + 8) * 64 + ol] =
                pack_f16x2((s0[nt][2] + b0) * QK_SCALE, (s0[nt][3] + b1) * QK_SCALE);
            *(uint32_t*)&dst[(size_t)(q + 16) * 64 + ol] =
                pack_f16x2((s1[nt][0] + b0) * QK_SCALE, (s1[nt][1] + b1) * QK_SCALE);
            *(uint32_t*)&dst[(size_t)(q + 24) * 64 + ol] =
                pack_f16x2((s1[nt][2] + b0) * QK_SCALE, (s1[nt][3] + b1) * QK_SCALE);
        }
    } else {
        __half (*sv)[136] = (__half(*)[136])smg;   // [64 o][128 t + pad]
        #pragma unroll
        for (int nt = 0; nt < 8; nt++) {
            int ol = nt * 8 + cc2;
            float b0 = bias[o0 + ol], b1 = bias[o0 + ol + 1];
            sv[ol][q]          = __float2half(s0[nt][0] + b0);
            sv[ol + 1][q]      = __float2half(s0[nt][1] + b1);
            sv[ol][q + 8]      = __float2half(s0[nt][2] + b0);
            sv[ol + 1][q + 8]  = __float2half(s0[nt][3] + b1);
            sv[ol][q + 16]     = __float2half(s1[nt][0] + b0);
            sv[ol + 1][q + 16] = __float2half(s1[nt][1] + b1);
            sv[ol][q + 24]     = __float2half(s1[nt][2] + b0);
            sv[ol + 1][q + 24] = __float2half(s1[nt][3] + b1);
        }
        __syncthreads();
        for (int i = threadIdx.x; i < 4096; i += 128) {
            int d = i >> 6, tp = (i & 63) * 2;
            uint32_t u = pack_f16x2(__half2float(sv[d][tp]), __half2float(sv[d][tp + 1]));
            *(uint32_t*)&g_vh[((size_t)bh * 64 + d) * TSEQ + t0 + tp] = u;
        }
    }
}

// ---------------------------------------------------------------------------
// Proj GEMM: 128t x 64o tiles + bias + residual, fp32 out [b][o][t].
// ---------------------------------------------------------------------------
__global__ void __launch_bounds__(128)
gemm_proj_h(const __half* __restrict__ Ht, const float* __restrict__ bias,
            const float* __restrict__ R, float* __restrict__ Y) {
    extern __shared__ __align__(128) char smg[];
    uint32_t sb = smem_to_u32(smg);
    int b_ = blockIdx.z, t0 = blockIdx.x * 128, o0 = blockIdx.y * 64;

    float s0[8][4], s1[8][4];
    gemm_mainloop2(sb,
        (const char*)(Ht + ((size_t)b_ * TSEQ + t0) * CDIM),
        (const char*)(g_wprojh + (size_t)o0 * CDIM), s0, s1);

    const int lane = threadIdx.x & 31, wid = threadIdx.x >> 5;
    int q   = wid * 32 + (lane >> 2);
    int cc2 = (lane & 3) * 2;

    float (*so)[132] = (float(*)[132])smg;   // [64 o][128 t + pad]
    #pragma unroll
    for (int nt = 0; nt < 8; nt++) {
        int ol = nt * 8 + cc2;
        so[ol][q]          = s0[nt][0];
        so[ol + 1][q]      = s0[nt][1];
        so[ol][q + 8]      = s0[nt][2];
        so[ol + 1][q + 8]  = s0[nt][3];
        so[ol][q + 16]     = s1[nt][0];
        so[ol + 1][q + 16] = s1[nt][1];
        so[ol][q + 24]     = s1[nt][2];
        so[ol + 1][q + 24] = s1[nt][3];
    }
    __syncthreads();
    for (int i = threadIdx.x; i < 2048; i += 128) {
        int o = i >> 5, t4 = (i & 31) * 4;
        size_t idx = ((size_t)(b_ * CDIM + o0 + o)) * TSEQ + t0 + t4;
        float4 rv = *(const float4*)&R[idx];
        float bvv = bias[o0 + o];
        float4 r;
        r.x = so[o][t4 + 0] + bvv + rv.x;
        r.y = so[o][t4 + 1] + bvv + rv.y;
        r.z = so[o][t4 + 2] + bvv + rv.z;
        r.w = so[o][t4 + 3] + bvv + rv.w;
        *(float4*)&Y[idx] = r;
    }
}

// ---------------------------------------------------------------------------
// Flash attention, fp16 mma.sync, SPLIT-KV x4. 128-query tile, 4 warps,
// 32 q-rows/warp, 64-key tiles (16 per split). Q lives in its OWN 16KB smem
// region so its load overlaps the first two K/V tile loads (wait<2> pattern).
// 3-stage K/V ring, one sync/iter. S in f16 accumulators, ex2 on packed D.
// Epilogue: UNNORMALIZED O (fp16) + l (fp32) partials to gmem.
// ---------------------------------------------------------------------------
__global__ void __launch_bounds__(128, 2)
attn_mma_kernel(const __half* __restrict__ Qh,
                const __half* __restrict__ Kh,
                const __half* __restrict__ Vh) {
    extern __shared__ __align__(128) char smem[];   // 16KB Q + 3x16KB stages
    uint32_t sb  = smem_to_u32(smem);
    uint32_t sbS = sb + 16384;                      // stage ring base
    const int tid = threadIdx.x, lane = tid & 31, wid = tid >> 5;
    const int bh = blockIdx.y, q0 = blockIdx.x * 128, sp = blockIdx.z;
    const int base = sp * SPT;

    const char* Kg = (const char*)(Kh + (size_t)bh * TSEQ * 64);
    const char* Vg = (const char*)(Vh + (size_t)bh * 64 * TSEQ);

    // Issue local tile ii (stage ii%3, global tile base+ii)
    auto issue = [&](int ii) {
        uint32_t dst = sbS + (uint32_t)(ii % 3) * 16384;
        int it = base + ii;
        const char* kg = Kg + (size_t)it * 64 * 128;
        #pragma unroll
        for (int p = 0; p < 4; p++) {
            int i = tid + p * 128;
            int row = i >> 3, c = i & 7;
            uint32_t soff = row * 128 + ((c ^ (row & 7)) * 16);
            cp_async16(dst + soff, kg + row * 128 + c * 16);
            cp_async16(dst + 8192 + soff, Vg + (size_t)row * 8192 + (size_t)it * 128 + c * 16);
        }
        cp_commit();
    };

    // ---- Q load (group 0) overlapped with tiles 0,1 (groups 1,2) ----
    {
        const char* Qg = (const char*)(Qh + ((size_t)bh * TSEQ + q0) * 64);
        #pragma unroll
        for (int p = 0; p < 8; p++) {
            int i = tid + p * 128;
            int row = i >> 3, c = i & 7;
            cp_async16(sb + row * 128 + ((c ^ (row & 7)) * 16), Qg + row * 128 + c * 16);
        }
        cp_commit();
    }
    issue(0);
    issue(1);

    cp_wait<2>();      // Q (oldest group) complete; tiles 0,1 still in flight
    __syncthreads();   // Q visible to all threads

    uint32_t qa0[4][4], qa1[4][4];
    {
        int r0 = wid * 32 + (lane & 7) + (((lane >> 3) & 1) << 3);
        int cbit = lane >> 4;
        uint32_t b0 = sb + r0 * 128;
        uint32_t b1 = sb + (r0 + 16) * 128;
        #pragma unroll
        for (int ks = 0; ks < 4; ks++) {
            uint32_t co = (((ks * 2 + cbit) ^ (r0 & 7)) << 4);
            ldm_x4(qa0[ks], b0 + co);
            ldm_x4(qa1[ks], b1 + co);
        }
    }
    // (Q region never overwritten; no further sync needed for it)

    const int rowB  = (lane & 7) + ((lane >> 4) << 3);
    const int cbitB = (lane >> 3) & 1;
    const uint32_t browoff = rowB * 128;

    float o0[8][4], o1[8][4];
    #pragma unroll
    for (int nt = 0; nt < 8; nt++)
        #pragma unroll
        for (int i = 0; i < 4; i++) { o0[nt][i] = 0.f; o1[nt][i] = 0.f; }
    float l0 = 0.f, l1 = 0.f, l2 = 0.f, l3 = 0.f;

    for (int ii = 0; ii < SPT; ii++) {
        if (ii < SPT - 1) cp_wait<1>(); else cp_wait<0>();
        __syncthreads();
        if (ii + 2 < SPT) issue(ii + 2);

        uint32_t kbase = sbS + (uint32_t)(ii % 3) * 16384 + browoff;
        uint32_t vbase = kbase + 8192;

        // S = Q·K^T for both 16-row sets, f16 accumulators.
        uint32_t sh0[8][2], sh1[8][2];
        #pragma unroll
        for (int nt = 0; nt < 8; nt++) {
            sh0[nt][0] = 0u; sh0[nt][1] = 0u;
            sh1[nt][0] = 0u; sh1[nt][1] = 0u;
        }

        #pragma unroll
        for (int ks = 0; ks < 4; ks++) {
            uint32_t coff = (((ks * 2 + cbitB) ^ (lane & 7)) << 4);
            #pragma unroll
            for (int nt2 = 0; nt2 < 4; nt2++) {
                uint32_t bfr[4];
                ldm_x4(bfr, kbase + nt2 * 2048 + coff);
                mma_f16acc(sh0[nt2 * 2 + 0], qa0[ks], bfr[0], bfr[1]);
                mma_f16acc(sh0[nt2 * 2 + 1], qa0[ks], bfr[2], bfr[3]);
                mma_f16acc(sh1[nt2 * 2 + 0], qa1[ks], bfr[0], bfr[1]);
                mma_f16acc(sh1[nt2 * 2 + 1], qa1[ks], bfr[2], bfr[3]);
            }
        }

        // P = 2^S: ex2 directly on packed f16 D regs -> A fragments.
        uint32_t pa0[4][4], pa1[4][4];
        #pragma unroll
        for (int jt = 0; jt < 4; jt++) {
            pa0[jt][0] = ex2_f16x2(sh0[2*jt][0]);
            pa0[jt][1] = ex2_f16x2(sh0[2*jt][1]);
            pa0[jt][2] = ex2_f16x2(sh0[2*jt+1][0]);
            pa0[jt][3] = ex2_f16x2(sh0[2*jt+1][1]);
            pa1[jt][0] = ex2_f16x2(sh1[2*jt][0]);
            pa1[jt][1] = ex2_f16x2(sh1[2*jt][1]);
            pa1[jt][2] = ex2_f16x2(sh1[2*jt+1][0]);
            pa1[jt][3] = ex2_f16x2(sh1[2*jt+1][1]);
        }
        {
            uint32_t a0 = hadd2(hadd2(pa0[0][0], pa0[1][0]), hadd2(pa0[2][0], pa0[3][0]));
            uint32_t a0b = hadd2(hadd2(pa0[0][2], pa0[1][2]), hadd2(pa0[2][2], pa0[3][2]));
            uint32_t a1 = hadd2(hadd2(pa0[0][1], pa0[1][1]), hadd2(pa0[2][1], pa0[3][1]));
            uint32_t a1b = hadd2(hadd2(pa0[0][3], pa0[1][3]), hadd2(pa0[2][3], pa0[3][3]));
            __half2 h0 = __hadd2(*(__half2*)&a0, *(__half2*)&a0b);
            __half2 h1 = __hadd2(*(__half2*)&a1, *(__half2*)&a1b);
            l0 += __low2float(h0) + __high2float(h0);
            l1 += __low2float(h1) + __high2float(h1);
            uint32_t c0 = hadd2(hadd2(pa1[0][0], pa1[1][0]), hadd2(pa1[2][0], pa1[3][0]));
            uint32_t c0b = hadd2(hadd2(pa1[0][2], pa1[1][2]), hadd2(pa1[2][2], pa1[3][2]));
            uint32_t c1 = hadd2(hadd2(pa1[0][1], pa1[1][1]), hadd2(pa1[2][1], pa1[3][1]));
            uint32_t c1b = hadd2(hadd2(pa1[0][3], pa1[1][3]), hadd2(pa1[2][3], pa1[3][3]));
            __half2 h2 = __hadd2(*(__half2*)&c0, *(__half2*)&c0b);
            __half2 h3 = __hadd2(*(__half2*)&c1, *(__half2*)&c1b);
            l2 += __low2float(h2) + __high2float(h2);
            l3 += __low2float(h3) + __high2float(h3);
        }

        // O += P·V^T (fp32 acc), sharing each V fragment
        #pragma unroll
        for (int jt = 0; jt < 4; jt++) {
            uint32_t coff = (((jt * 2 + cbitB) ^ (lane & 7)) << 4);
            #pragma unroll
            for (int nt2 = 0; nt2 < 4; nt2++) {
                uint32_t bfr[4];
                ldm_x4(bfr, vbase + nt2 * 2048 + coff);
                mma_f16(o0[nt2 * 2 + 0], pa0[jt], bfr[0], bfr[1]);
                mma_f16(o0[nt2 * 2 + 1], pa0[jt], bfr[2], bfr[3]);
                mma_f16(o1[nt2 * 2 + 0], pa1[jt], bfr[0], bfr[1]);
                mma_f16(o1[nt2 * 2 + 1], pa1[jt], bfr[2], bfr[3]);
            }
        }
    }

    // Quad reduce l; store UNNORMALIZED O (fp16) and l (fp32) partials.
    #pragma unroll
    for (int off = 1; off <= 2; off <<= 1) {
        l0 += __shfl_xor_sync(0xffffffffu, l0, off);
        l1 += __shfl_xor_sync(0xffffffffu, l1, off);
        l2 += __shfl_xor_sync(0xffffffffu, l2, off);
        l3 += __shfl_xor_sync(0xffffffffu, l3, off);
    }

    int q  = wid * 32 + (lane >> 2);
    int cc = (lane & 3) * 2;
    __half* op = g_op + ((size_t)(sp * 8 + bh) * TSEQ + q0) * 64;
    #pragma unroll
    for (int nt = 0; nt < 8; nt++) {
        int d0 = nt * 8 + cc;
        *(uint32_t*)&op[(size_t)q * 64 + d0]        = pack_f16x2(o0[nt][0], o0[nt][1]);
        *(uint32_t*)&op[(size_t)(q + 8) * 64 + d0]  = pack_f16x2(o0[nt][2], o0[nt][3]);
        *(uint32_t*)&op[(size_t)(q + 16) * 64 + d0] = pack_f16x2(o1[nt][0], o1[nt][1]);
        *(uint32_t*)&op[(size_t)(q + 24) * 64 + d0] = pack_f16x2(o1[nt][2], o1[nt][3]);
    }
    if ((lane & 3) == 0) {
        float* lp = g_lp + (size_t)(sp * 8 + bh) * TSEQ + q0;
        lp[q] = l0; lp[q + 8] = l1; lp[q + 16] = l2; lp[q + 24] = l3;
    }
}

// ---------------------------------------------------------------------------
// Split-KV combine: h[row][d] = (sum_s O_s) / (sum_s l_s), emit hT fp16.
// ---------------------------------------------------------------------------
__global__ void attn_combine_kernel() {
    int gid = blockIdx.x * 256 + threadIdx.x;   // 524288
    int row = gid >> 4;
    int d4  = (gid & 15) * 4;

    float l = g_lp[row] + g_lp[32768 + row] + g_lp[65536 + row] + g_lp[98304 + row];
    float inv = 1.f / l;

    float a0 = 0.f, a1 = 0.f, a2 = 0.f, a3 = 0.f;
    #pragma unroll
    for (int s = 0; s < NSPLIT; s++) {
        uint2 u = *(const uint2*)&g_op[((size_t)s * 8 * TSEQ + row) * 64 + d4];
        __half2 x = *(__half2*)&u.x, y = *(__half2*)&u.y;
        a0 += __low2float(x); a1 += __high2float(x);
        a2 += __low2float(y); a3 += __high2float(y);
    }
    int bh = row >> 12, t = row & 4095;
    uint2 o;
    o.x = pack_f16x2(a0 * inv, a1 * inv);
    o.y = pack_f16x2(a2 * inv, a3 * inv);
    *(uint2*)&g_hh[((size_t)(bh >> 2) * TSEQ + t) * CDIM + (bh & 3) * 64 + d4] = o;
}

// ---------------------------------------------------------------------------
// Launch
// ---------------------------------------------------------------------------
extern "C" void kernel_launch(void* const* d_in, const int* in_sizes, int n_in,
                              void* d_out, int out_size) {
    const float* x      = (const float*)d_in[0];
    const float* gn_w   = (const float*)d_in[1];
    const float* gn_b   = (const float*)d_in[2];
    const float* qkv_w  = (const float*)d_in[3];
    const float* qkv_b  = (const float*)d_in[4];
    const float* proj_w = (const float*)d_in[5];
    const float* proj_b = (const float*)d_in[6];
    float* out = (float*)d_out;

    __half *xnh, *hh, *qh, *kh, *vh;
    cudaGetSymbolAddress((void**)&xnh, g_xnh);
    cudaGetSymbolAddress((void**)&hh,  g_hh);
    cudaGetSymbolAddress((void**)&qh,  g_qh);
    cudaGetSymbolAddress((void**)&kh,  g_kh);
    cudaGetSymbolAddress((void**)&vh,  g_vh);

    cudaFuncSetAttribute(gemm_qkv_h,
                         cudaFuncAttributeMaxDynamicSharedMemorySize, GEMM_SMEM);
    cudaFuncSetAttribute(gemm_proj_h,
                         cudaFuncAttributeMaxDynamicSharedMemorySize, GEMM_SMEM);
    cudaFuncSetAttribute(attn_mma_kernel,
                         cudaFuncAttributeMaxDynamicSharedMemorySize, ATT_SMEM);

    gn_stats_kernel<<<64, 256>>>(x, qkv_w, proj_w);
    gn_apply_t_kernel<<<dim3(4, 64, 2), 256>>>(x, gn_w, gn_b);
    gemm_qkv_h<<<dim3(32, 12, 2), 128, GEMM_SMEM>>>(xnh, qkv_b);
    attn_mma_kernel<<<dim3(32, 8, NSPLIT), 128, ATT_SMEM>>>(qh, kh, vh);
    attn_combine_kernel<<<2048, 256>>>();
    gemm_proj_h<<<dim3(32, 4, 2), 128, GEMM_SMEM>>>(hh, proj_b, x, out);
}

// round 17
// speedup vs baseline: 1.0131x; 1.0010x over previous
#include <cuda_runtime.h>
#include <cuda_fp16.h>
#include <math.h>
#include <cstdint>

// ---------------------------------------------------------------------------
// Problem constants
// ---------------------------------------------------------------------------
static constexpr int BATCH = 2;
static constexpr int CDIM  = 256;
static constexpr int TSEQ  = 4096;   // 64*64
// 64^-0.25 * sqrt(log2(e)) : folds the exp->exp2 conversion into Q and K
static constexpr float QK_SCALE = 0.42466090936113257f;
static constexpr int NTILES = TSEQ / 64;  // 64 kv tiles of 64 keys
static constexpr int NSPLIT = 4;
static constexpr int SPT = NTILES / NSPLIT;  // 16 tiles per split

static constexpr int GEMM_SMEM = 3 * 24576;      // GEMMs: 72 KB 3-stage ring
static constexpr int ATT_SMEM  = 16384 + 4 * 16384;  // attn: Q 16KB + 4x16KB stages

// Scratch (device globals; allocation-free)
__device__ __half g_xnh[BATCH * TSEQ * CDIM];  // GN out, [b][t][c] 4 MB
__device__ __half g_hh [BATCH * TSEQ * CDIM];  // attn out, [b][t][c] 4 MB
__device__ __half g_qh[8 * TSEQ * 64];         // [bh][t][c] 4 MB
__device__ __half g_kh[8 * TSEQ * 64];         // [bh][t][c] 4 MB
__device__ __half g_vh[8 * 64 * TSEQ];         // [bh][d][t] 4 MB
__device__ __half g_wqkvh[768 * 256];          // fp16 qkv weight
__device__ __half g_wprojh[256 * 256];         // fp16 proj weight
__device__ __half g_op[NSPLIT * 8 * TSEQ * 64]; // unnormalized O partials 16.8MB
__device__ float  g_lp[NSPLIT * 8 * TSEQ];      // l partials 512KB
__device__ float g_mean[64];
__device__ float g_rstd[64];

// ---------------------------------------------------------------------------
// PTX helpers (sm_80+ subset: mma.sync / ldmatrix / cp.async)
// ---------------------------------------------------------------------------
__device__ __forceinline__ uint32_t smem_to_u32(const void* p) {
    uint32_t a;
    asm("{ .reg .u64 t; cvta.to.shared.u64 t, %1; cvt.u32.u64 %0, t; }" : "=r"(a) : "l"(p));
    return a;
}

__device__ __forceinline__ void cp_async16(uint32_t saddr, const void* gaddr) {
    asm volatile("cp.async.cg.shared.global [%0], [%1], 16;" :: "r"(saddr), "l"(gaddr));
}
__device__ __forceinline__ void cp_commit() { asm volatile("cp.async.commit_group;"); }
template <int N>
__device__ __forceinline__ void cp_wait() { asm volatile("cp.async.wait_group %0;" :: "n"(N)); }

__device__ __forceinline__ void ldm_x4(uint32_t* r, uint32_t addr) {
    asm volatile("ldmatrix.sync.aligned.m8n8.x4.shared.b16 {%0,%1,%2,%3}, [%4];"
        : "=r"(r[0]), "=r"(r[1]), "=r"(r[2]), "=r"(r[3]) : "r"(addr));
}

__device__ __forceinline__ void mma_f16(float* c, const uint32_t* a, uint32_t b0, uint32_t b1) {
    asm volatile("mma.sync.aligned.m16n8k16.row.col.f32.f16.f16.f32 "
        "{%0,%1,%2,%3}, {%4,%5,%6,%7}, {%8,%9}, {%0,%1,%2,%3};"
        : "+f"(c[0]), "+f"(c[1]), "+f"(c[2]), "+f"(c[3])
        : "r"(a[0]), "r"(a[1]), "r"(a[2]), "r"(a[3]), "r"(b0), "r"(b1));
}

// f16 accumulator variant: D/C are 2 packed f16x2 regs.
__device__ __forceinline__ void mma_f16acc(uint32_t* c, const uint32_t* a, uint32_t b0, uint32_t b1) {
    asm volatile("mma.sync.aligned.m16n8k16.row.col.f16.f16.f16.f16 "
        "{%0,%1}, {%2,%3,%4,%5}, {%6,%7}, {%0,%1};"
        : "+r"(c[0]), "+r"(c[1])
        : "r"(a[0]), "r"(a[1]), "r"(a[2]), "r"(a[3]), "r"(b0), "r"(b1));
}

__device__ __forceinline__ uint32_t pack_f16x2(float lo, float hi) {
    uint32_t r;
    asm("cvt.rn.f16x2.f32 %0, %1, %2;" : "=r"(r) : "f"(hi), "f"(lo));
    return r;
}
__device__ __forceinline__ uint32_t ex2_f16x2(uint32_t a) {
    uint32_t r;
    asm("ex2.approx.f16x2 %0, %1;" : "=r"(r) : "r"(a));
    return r;
}
__device__ __forceinline__ uint32_t hadd2(uint32_t a, uint32_t b) {
    uint32_t r;
    asm("add.f16x2 %0, %1, %2;" : "=r"(r) : "r"(a), "r"(b));
    return r;
}

// ---------------------------------------------------------------------------
// GroupNorm stats + weight fp32->fp16 conversion (folded).
// ---------------------------------------------------------------------------
__global__ void gn_stats_kernel(const float* __restrict__ x,
                                const float* __restrict__ qkvw,
                                const float* __restrict__ projw) {
    int gtid = blockIdx.x * 256 + threadIdx.x;   // 0..16383
    #pragma unroll
    for (int p = 0; p < 6; p++) {
        int i = gtid + p * 16384;
        float2 v = *(const float2*)&qkvw[(size_t)i * 2];
        *(uint32_t*)&g_wqkvh[(size_t)i * 2] = pack_f16x2(v.x, v.y);
    }
    #pragma unroll
    for (int p = 0; p < 2; p++) {
        int i = gtid + p * 16384;
        float2 v = *(const float2*)&projw[(size_t)i * 2];
        *(uint32_t*)&g_wprojh[(size_t)i * 2] = pack_f16x2(v.x, v.y);
    }

    int bg = blockIdx.x;
    const float4* p = (const float4*)(x + (size_t)bg * 32768);
    float s = 0.f, s2 = 0.f;
    for (int i = threadIdx.x; i < 8192; i += 256) {
        float4 v = p[i];
        s  += v.x + v.y + v.z + v.w;
        s2 += v.x*v.x + v.y*v.y + v.z*v.z + v.w*v.w;
    }
    #pragma unroll
    for (int off = 16; off; off >>= 1) {
        s  += __shfl_xor_sync(0xffffffffu, s,  off);
        s2 += __shfl_xor_sync(0xffffffffu, s2, off);
    }
    __shared__ float as[8], bs[8];
    int w = threadIdx.x >> 5, lane = threadIdx.x & 31;
    if (lane == 0) { as[w] = s; bs[w] = s2; }
    __syncthreads();
    if (threadIdx.x == 0) {
        float ts = 0.f, t2 = 0.f;
        #pragma unroll
        for (int i = 0; i < 8; i++) { ts += as[i]; t2 += bs[i]; }
        float mu  = ts * (1.f / 32768.f);
        float var = t2 * (1.f / 32768.f) - mu * mu;
        g_mean[bg] = mu;
        g_rstd[bg] = rsqrtf(var + 1e-5f);
    }
}

// ---------------------------------------------------------------------------
// GroupNorm apply + transpose: x [b][c][t] fp32 -> g_xnh [b][t][c] fp16.
// ---------------------------------------------------------------------------
__global__ void gn_apply_t_kernel(const float* __restrict__ x,
                                  const float* __restrict__ w,
                                  const float* __restrict__ b) {
    __shared__ float tile[64][68];
    int b_ = blockIdx.z, c0 = blockIdx.x * 64, t0 = blockIdx.y * 64;

    #pragma unroll
    for (int p = 0; p < 4; p++) {
        int i = threadIdx.x + p * 256;
        int c = i >> 4, t4 = (i & 15) * 4;
        int cg = c0 + c;
        int bg = b_ * 32 + (cg >> 3);
        float sw = w[cg] * g_rstd[bg];
        float sb = b[cg] - g_mean[bg] * sw;
        float4 v = *(const float4*)&x[((size_t)(b_ * CDIM + cg)) * TSEQ + t0 + t4];
        tile[c][t4 + 0] = v.x * sw + sb;
        tile[c][t4 + 1] = v.y * sw + sb;
        tile[c][t4 + 2] = v.z * sw + sb;
        tile[c][t4 + 3] = v.w * sw + sb;
    }
    __syncthreads();

    #pragma unroll
    for (int p = 0; p < 8; p++) {
        int i = threadIdx.x + p * 256;
        int t = i >> 5, cp = (i & 31) * 2;
        uint32_t u = pack_f16x2(tile[cp][t], tile[cp + 1][t]);
        *(uint32_t*)&g_xnh[((size_t)(b_ * TSEQ + t0 + t)) * CDIM + c0 + cp] = u;
    }
}

// ---------------------------------------------------------------------------
// Shared fp16 TN GEMM mainloop, 128(t) x 64(o) tile, 4 warps x 32 t-rows.
// 3-stage cp.async ring (24KB stages), one sync per K-chunk.
// ---------------------------------------------------------------------------
__device__ __forceinline__ void gemm_mainloop2(
    uint32_t sb, const char* Ag, const char* Bg,
    float (*s0)[4], float (*s1)[4]) {
    const int tid = threadIdx.x, lane = tid & 31, wid = tid >> 5;
    const int r0    = wid * 32 + (lane & 7) + (((lane >> 3) & 1) << 3);
    const int cbitA = lane >> 4;
    const int rowB  = (lane & 7) + ((lane >> 4) << 3);
    const int cbitB = (lane >> 3) & 1;
    const uint32_t brow = rowB * 128;

    #pragma unroll
    for (int nt = 0; nt < 8; nt++)
        #pragma unroll
        for (int i = 0; i < 4; i++) { s0[nt][i] = 0.f; s1[nt][i] = 0.f; }

    auto issue = [&](int kc) {
        uint32_t dst = sb + (uint32_t)(kc % 3) * 24576;
        #pragma unroll
        for (int p = 0; p < 8; p++) {
            int i = tid + p * 128;
            int row = i >> 3, c = i & 7;
            uint32_t soff = row * 128 + ((c ^ (row & 7)) * 16);
            cp_async16(dst + soff, Ag + (size_t)row * 512 + kc * 128 + c * 16);
        }
        #pragma unroll
        for (int p = 0; p < 4; p++) {
            int i = tid + p * 128;
            int row = i >> 3, c = i & 7;
            uint32_t soff = row * 128 + ((c ^ (row & 7)) * 16);
            cp_async16(dst + 16384 + soff, Bg + (size_t)row * 512 + kc * 128 + c * 16);
        }
        cp_commit();
    };

    issue(0);
    issue(1);
    #pragma unroll
    for (int kc = 0; kc < 4; kc++) {
        if (kc < 3) cp_wait<1>(); else cp_wait<0>();
        __syncthreads();
        if (kc + 2 < 4) issue(kc + 2);
        uint32_t abase = sb + (uint32_t)(kc % 3) * 24576;
        uint32_t a0 = abase + r0 * 128;
        uint32_t a1 = abase + (r0 + 16) * 128;
        uint32_t kbase = abase + 16384 + brow;
        #pragma unroll
        for (int ks = 0; ks < 4; ks++) {
            uint32_t qa0[4], qa1[4];
            uint32_t co = (((ks * 2 + cbitA) ^ (r0 & 7)) << 4);
            ldm_x4(qa0, a0 + co);
            ldm_x4(qa1, a1 + co);
            uint32_t coffB = (((ks * 2 + cbitB) ^ (lane & 7)) << 4);
            #pragma unroll
            for (int nt2 = 0; nt2 < 4; nt2++) {
                uint32_t bfr[4];
                ldm_x4(bfr, kbase + nt2 * 2048 + coffB);
                mma_f16(s0[nt2 * 2 + 0], qa0, bfr[0], bfr[1]);
                mma_f16(s0[nt2 * 2 + 1], qa0, bfr[2], bfr[3]);
                mma_f16(s1[nt2 * 2 + 0], qa1, bfr[0], bfr[1]);
                mma_f16(s1[nt2 * 2 + 1], qa1, bfr[2], bfr[3]);
            }
        }
    }
    __syncthreads();   // before epilogue reuses smem
}

// ---------------------------------------------------------------------------
// QKV GEMM: 128t x 64o tiles. Epilogue routes to Q/K [bh][t][c] (scaled)
// directly from fragments, or V [bh][d][t] via smem transpose.
// ---------------------------------------------------------------------------
__global__ void __launch_bounds__(128)
gemm_qkv_h(const __half* __restrict__ Xt, const float* __restrict__ bias) {
    extern __shared__ __align__(128) char smg[];
    uint32_t sb = smem_to_u32(smg);
    int b_ = blockIdx.z, t0 = blockIdx.x * 128, o0 = blockIdx.y * 64;

    float s0[8][4], s1[8][4];
    gemm_mainloop2(sb,
        (const char*)(Xt + ((size_t)b_ * TSEQ + t0) * CDIM),
        (const char*)(g_wqkvh + (size_t)o0 * CDIM), s0, s1);

    const int lane = threadIdx.x & 31, wid = threadIdx.x >> 5;
    int q   = wid * 32 + (lane >> 2);
    int cc2 = (lane & 3) * 2;

    int h    = o0 / 192;
    int type = (o0 % 192) / 64;   // 0=Q 1=K 2=V
    int bh   = b_ * 4 + h;

    if (type < 2) {
        __half* dst = ((type == 0) ? g_qh : g_kh) + ((size_t)bh * TSEQ + t0) * 64;
        #pragma unroll
        for (int nt = 0; nt < 8; nt++) {
            int ol = nt * 8 + cc2;
            float b0 = bias[o0 + ol], b1 = bias[o0 + ol + 1];
            *(uint32_t*)&dst[(size_t)q * 64 + ol] =
                pack_f16x2((s0[nt][0] + b0) * QK_SCALE, (s0[nt][1] + b1) * QK_SCALE);
            *(uint32_t*)&dst[(size_t)(q + 8) * 64 + ol] =
                pack_f16x2((s0[nt][2] + b0) * QK_SCALE, (s0[nt][3] + b1) * QK_SCALE);
            *(uint32_t*)&dst[(size_t)(q + 16) * 64 + ol] =
                pack_f16x2((s1[nt][0] + b0) * QK_SCALE, (s1[nt][1] + b1) * QK_SCALE);
            *(uint32_t*)&dst[(size_t)(q + 24) * 64 + ol] =
                pack_f16x2((s1[nt][2] + b0) * QK_SCALE, (s1[nt][3] + b1) * QK_SCALE);
        }
    } else {
        __half (*sv)[136] = (__half(*)[136])smg;   // [64 o][128 t + pad]
        #pragma unroll
        for (int nt = 0; nt < 8; nt++) {
            int ol = nt * 8 + cc2;
            float b0 = bias[o0 + ol], b1 = bias[o0 + ol + 1];
            sv[ol][q]          = __float2half(s0[nt][0] + b0);
            sv[ol + 1][q]      = __float2half(s0[nt][1] + b1);
            sv[ol][q + 8]      = __float2half(s0[nt][2] + b0);
            sv[ol + 1][q + 8]  = __float2half(s0[nt][3] + b1);
            sv[ol][q + 16]     = __float2half(s1[nt][0] + b0);
            sv[ol + 1][q + 16] = __float2half(s1[nt][1] + b1);
            sv[ol][q + 24]     = __float2half(s1[nt][2] + b0);
            sv[ol + 1][q + 24] = __float2half(s1[nt][3] + b1);
        }
        __syncthreads();
        for (int i = threadIdx.x; i < 4096; i += 128) {
            int d = i >> 6, tp = (i & 63) * 2;
            uint32_t u = pack_f16x2(__half2float(sv[d][tp]), __half2float(sv[d][tp + 1]));
            *(uint32_t*)&g_vh[((size_t)bh * 64 + d) * TSEQ + t0 + tp] = u;
        }
    }
}

// ---------------------------------------------------------------------------
// Proj GEMM: 128t x 64o tiles + bias + residual, fp32 out [b][o][t].
// ---------------------------------------------------------------------------
__global__ void __launch_bounds__(128)
gemm_proj_h(const __half* __restrict__ Ht, const float* __restrict__ bias,
            const float* __restrict__ R, float* __restrict__ Y) {
    extern __shared__ __align__(128) char smg[];
    uint32_t sb = smem_to_u32(smg);
    int b_ = blockIdx.z, t0 = blockIdx.x * 128, o0 = blockIdx.y * 64;

    float s0[8][4], s1[8][4];
    gemm_mainloop2(sb,
        (const char*)(Ht + ((size_t)b_ * TSEQ + t0) * CDIM),
        (const char*)(g_wprojh + (size_t)o0 * CDIM), s0, s1);

    const int lane = threadIdx.x & 31, wid = threadIdx.x >> 5;
    int q   = wid * 32 + (lane >> 2);
    int cc2 = (lane & 3) * 2;

    float (*so)[132] = (float(*)[132])smg;   // [64 o][128 t + pad]
    #pragma unroll
    for (int nt = 0; nt < 8; nt++) {
        int ol = nt * 8 + cc2;
        so[ol][q]          = s0[nt][0];
        so[ol + 1][q]      = s0[nt][1];
        so[ol][q + 8]      = s0[nt][2];
        so[ol + 1][q + 8]  = s0[nt][3];
        so[ol][q + 16]     = s1[nt][0];
        so[ol + 1][q + 16] = s1[nt][1];
        so[ol][q + 24]     = s1[nt][2];
        so[ol + 1][q + 24] = s1[nt][3];
    }
    __syncthreads();
    for (int i = threadIdx.x; i < 2048; i += 128) {
        int o = i >> 5, t4 = (i & 31) * 4;
        size_t idx = ((size_t)(b_ * CDIM + o0 + o)) * TSEQ + t0 + t4;
        float4 rv = *(const float4*)&R[idx];
        float bvv = bias[o0 + o];
        float4 r;
        r.x = so[o][t4 + 0] + bvv + rv.x;
        r.y = so[o][t4 + 1] + bvv + rv.y;
        r.z = so[o][t4 + 2] + bvv + rv.z;
        r.w = so[o][t4 + 3] + bvv + rv.w;
        *(float4*)&Y[idx] = r;
    }
}

// ---------------------------------------------------------------------------
// Flash attention, fp16 mma.sync, SPLIT-KV x4. 128-query tile, 4 warps,
// 32 q-rows/warp, 64-key tiles (16 per split). Q in its own 16KB region
// (load overlapped with first tiles). FOUR-stage K/V ring: 3 tiles in
// flight, stage index ii&3 (compile-time under unroll 4). One sync/iter.
// S in f16 accumulators, ex2 on packed D regs.
// Epilogue: UNNORMALIZED O (fp16) + l (fp32) partials to gmem.
// ---------------------------------------------------------------------------
__global__ void __launch_bounds__(128, 2)
attn_mma_kernel(const __half* __restrict__ Qh,
                const __half* __restrict__ Kh,
                const __half* __restrict__ Vh) {
    extern __shared__ __align__(128) char smem[];   // 16KB Q + 4x16KB stages
    uint32_t sb  = smem_to_u32(smem);
    uint32_t sbS = sb + 16384;                      // stage ring base
    const int tid = threadIdx.x, lane = tid & 31, wid = tid >> 5;
    const int bh = blockIdx.y, q0 = blockIdx.x * 128, sp = blockIdx.z;
    const int base = sp * SPT;

    const char* Kg = (const char*)(Kh + (size_t)bh * TSEQ * 64);
    const char* Vg = (const char*)(Vh + (size_t)bh * 64 * TSEQ);

    // Issue local tile ii into stage ii&3 (global tile base+ii)
    auto issue = [&](int ii) {
        uint32_t dst = sbS + (uint32_t)(ii & 3) * 16384;
        int it = base + ii;
        const char* kg = Kg + (size_t)it * 64 * 128;
        #pragma unroll
        for (int p = 0; p < 4; p++) {
            int i = tid + p * 128;
            int row = i >> 3, c = i & 7;
            uint32_t soff = row * 128 + ((c ^ (row & 7)) * 16);
            cp_async16(dst + soff, kg + row * 128 + c * 16);
            cp_async16(dst + 8192 + soff, Vg + (size_t)row * 8192 + (size_t)it * 128 + c * 16);
        }
        cp_commit();
    };

    // ---- Q load (group 0) overlapped with tiles 0,1,2 (groups 1..3) ----
    {
        const char* Qg = (const char*)(Qh + ((size_t)bh * TSEQ + q0) * 64);
        #pragma unroll
        for (int p = 0; p < 8; p++) {
            int i = tid + p * 128;
            int row = i >> 3, c = i & 7;
            cp_async16(sb + row * 128 + ((c ^ (row & 7)) * 16), Qg + row * 128 + c * 16);
        }
        cp_commit();
    }
    issue(0);
    issue(1);
    issue(2);

    cp_wait<3>();      // Q (oldest group) complete; tiles 0..2 in flight
    __syncthreads();   // Q visible to all threads

    uint32_t qa0[4][4], qa1[4][4];
    {
        int r0 = wid * 32 + (lane & 7) + (((lane >> 3) & 1) << 3);
        int cbit = lane >> 4;
        uint32_t b0 = sb + r0 * 128;
        uint32_t b1 = sb + (r0 + 16) * 128;
        #pragma unroll
        for (int ks = 0; ks < 4; ks++) {
            uint32_t co = (((ks * 2 + cbit) ^ (r0 & 7)) << 4);
            ldm_x4(qa0[ks], b0 + co);
            ldm_x4(qa1[ks], b1 + co);
        }
    }
    // (Q region never overwritten; no further sync needed for it)

    const int rowB  = (lane & 7) + ((lane >> 4) << 3);
    const int cbitB = (lane >> 3) & 1;
    const uint32_t browoff = rowB * 128;

    float o0[8][4], o1[8][4];
    #pragma unroll
    for (int nt = 0; nt < 8; nt++)
        #pragma unroll
        for (int i = 0; i < 4; i++) { o0[nt][i] = 0.f; o1[nt][i] = 0.f; }
    float l0 = 0.f, l1 = 0.f, l2 = 0.f, l3 = 0.f;

    #pragma unroll 4
    for (int ii = 0; ii < SPT; ii++) {
        if (ii < SPT - 2) cp_wait<2>();
        else if (ii == SPT - 2) cp_wait<1>();
        else cp_wait<0>();
        __syncthreads();                  // all warps done with stage (ii-1)&3
        if (ii + 3 < SPT) issue(ii + 3);  // writes stage (ii+3)&3 == (ii-1)&3

        uint32_t kbase = sbS + (uint32_t)(ii & 3) * 16384 + browoff;
        uint32_t vbase = kbase + 8192;

        // S = Q·K^T for both 16-row sets, f16 accumulators.
        uint32_t sh0[8][2], sh1[8][2];
        #pragma unroll
        for (int nt = 0; nt < 8; nt++) {
            sh0[nt][0] = 0u; sh0[nt][1] = 0u;
            sh1[nt][0] = 0u; sh1[nt][1] = 0u;
        }

        #pragma unroll
        for (int ks = 0; ks < 4; ks++) {
            uint32_t coff = (((ks * 2 + cbitB) ^ (lane & 7)) << 4);
            #pragma unroll
            for (int nt2 = 0; nt2 < 4; nt2++) {
                uint32_t bfr[4];
                ldm_x4(bfr, kbase + nt2 * 2048 + coff);
                mma_f16acc(sh0[nt2 * 2 + 0], qa0[ks], bfr[0], bfr[1]);
                mma_f16acc(sh0[nt2 * 2 + 1], qa0[ks], bfr[2], bfr[3]);
                mma_f16acc(sh1[nt2 * 2 + 0], qa1[ks], bfr[0], bfr[1]);
                mma_f16acc(sh1[nt2 * 2 + 1], qa1[ks], bfr[2], bfr[3]);
            }
        }

        // P = 2^S: ex2 directly on packed f16 D regs -> A fragments.
        uint32_t pa0[4][4], pa1[4][4];
        #pragma unroll
        for (int jt = 0; jt < 4; jt++) {
            pa0[jt][0] = ex2_f16x2(sh0[2*jt][0]);
            pa0[jt][1] = ex2_f16x2(sh0[2*jt][1]);
            pa0[jt][2] = ex2_f16x2(sh0[2*jt+1][0]);
            pa0[jt][3] = ex2_f16x2(sh0[2*jt+1][1]);
            pa1[jt][0] = ex2_f16x2(sh1[2*jt][0]);
            pa1[jt][1] = ex2_f16x2(sh1[2*jt][1]);
            pa1[jt][2] = ex2_f16x2(sh1[2*jt+1][0]);
            pa1[jt][3] = ex2_f16x2(sh1[2*jt+1][1]);
        }
        {
            uint32_t a0 = hadd2(hadd2(pa0[0][0], pa0[1][0]), hadd2(pa0[2][0], pa0[3][0]));
            uint32_t a0b = hadd2(hadd2(pa0[0][2], pa0[1][2]), hadd2(pa0[2][2], pa0[3][2]));
            uint32_t a1 = hadd2(hadd2(pa0[0][1], pa0[1][1]), hadd2(pa0[2][1], pa0[3][1]));
            uint32_t a1b = hadd2(hadd2(pa0[0][3], pa0[1][3]), hadd2(pa0[2][3], pa0[3][3]));
            __half2 h0 = __hadd2(*(__half2*)&a0, *(__half2*)&a0b);
            __half2 h1 = __hadd2(*(__half2*)&a1, *(__half2*)&a1b);
            l0 += __low2float(h0) + __high2float(h0);
            l1 += __low2float(h1) + __high2float(h1);
            uint32_t c0 = hadd2(hadd2(pa1[0][0], pa1[1][0]), hadd2(pa1[2][0], pa1[3][0]));
            uint32_t c0b = hadd2(hadd2(pa1[0][2], pa1[1][2]), hadd2(pa1[2][2], pa1[3][2]));
            uint32_t c1 = hadd2(hadd2(pa1[0][1], pa1[1][1]), hadd2(pa1[2][1], pa1[3][1]));
            uint32_t c1b = hadd2(hadd2(pa1[0][3], pa1[1][3]), hadd2(pa1[2][3], pa1[3][3]));
            __half2 h2 = __hadd2(*(__half2*)&c0, *(__half2*)&c0b);
            __half2 h3 = __hadd2(*(__half2*)&c1, *(__half2*)&c1b);
            l2 += __low2float(h2) + __high2float(h2);
            l3 += __low2float(h3) + __high2float(h3);
        }

        // O += P·V^T (fp32 acc), sharing each V fragment
        #pragma unroll
        for (int jt = 0; jt < 4; jt++) {
            uint32_t coff = (((jt * 2 + cbitB) ^ (lane & 7)) << 4);
            #pragma unroll
            for (int nt2 = 0; nt2 < 4; nt2++) {
                uint32_t bfr[4];
                ldm_x4(bfr, vbase + nt2 * 2048 + coff);
                mma_f16(o0[nt2 * 2 + 0], pa0[jt], bfr[0], bfr[1]);
                mma_f16(o0[nt2 * 2 + 1], pa0[jt], bfr[2], bfr[3]);
                mma_f16(o1[nt2 * 2 + 0], pa1[jt], bfr[0], bfr[1]);
                mma_f16(o1[nt2 * 2 + 1], pa1[jt], bfr[2], bfr[3]);
            }
        }
    }

    // Quad reduce l; store UNNORMALIZED O (fp16) and l (fp32) partials.
    #pragma unroll
    for (int off = 1; off <= 2; off <<= 1) {
        l0 += __shfl_xor_sync(0xffffffffu, l0, off);
        l1 += __shfl_xor_sync(0xffffffffu, l1, off);
        l2 += __shfl_xor_sync(0xffffffffu, l2, off);
        l3 += __shfl_xor_sync(0xffffffffu, l3, off);
    }

    int q  = wid * 32 + (lane >> 2);
    int cc = (lane & 3) * 2;
    __half* op = g_op + ((size_t)(sp * 8 + bh) * TSEQ + q0) * 64;
    #pragma unroll
    for (int nt = 0; nt < 8; nt++) {
        int d0 = nt * 8 + cc;
        *(uint32_t*)&op[(size_t)q * 64 + d0]        = pack_f16x2(o0[nt][0], o0[nt][1]);
        *(uint32_t*)&op[(size_t)(q + 8) * 64 + d0]  = pack_f16x2(o0[nt][2], o0[nt][3]);
        *(uint32_t*)&op[(size_t)(q + 16) * 64 + d0] = pack_f16x2(o1[nt][0], o1[nt][1]);
        *(uint32_t*)&op[(size_t)(q + 24) * 64 + d0] = pack_f16x2(o1[nt][2], o1[nt][3]);
    }
    if ((lane & 3) == 0) {
        float* lp = g_lp + (size_t)(sp * 8 + bh) * TSEQ + q0;
        lp[q] = l0; lp[q + 8] = l1; lp[q + 16] = l2; lp[q + 24] = l3;
    }
}

// ---------------------------------------------------------------------------
// Split-KV combine: h[row][d] = (sum_s O_s) / (sum_s l_s), emit hT fp16.
// ---------------------------------------------------------------------------
__global__ void attn_combine_kernel() {
    int gid = blockIdx.x * 256 + threadIdx.x;   // 524288
    int row = gid >> 4;
    int d4  = (gid & 15) * 4;

    float l = g_lp[row] + g_lp[32768 + row] + g_lp[65536 + row] + g_lp[98304 + row];
    float inv = 1.f / l;

    float a0 = 0.f, a1 = 0.f, a2 = 0.f, a3 = 0.f;
    #pragma unroll
    for (int s = 0; s < NSPLIT; s++) {
        uint2 u = *(const uint2*)&g_op[((size_t)s * 8 * TSEQ + row) * 64 + d4];
        __half2 x = *(__half2*)&u.x, y = *(__half2*)&u.y;
        a0 += __low2float(x); a1 += __high2float(x);
        a2 += __low2float(y); a3 += __high2float(y);
    }
    int bh = row >> 12, t = row & 4095;
    uint2 o;
    o.x = pack_f16x2(a0 * inv, a1 * inv);
    o.y = pack_f16x2(a2 * inv, a3 * inv);
    *(uint2*)&g_hh[((size_t)(bh >> 2) * TSEQ + t) * CDIM + (bh & 3) * 64 + d4] = o;
}

// ---------------------------------------------------------------------------
// Launch
// ---------------------------------------------------------------------------
extern "C" void kernel_launch(void* const* d_in, const int* in_sizes, int n_in,
                              void* d_out, int out_size) {
    const float* x      = (const float*)d_in[0];
    const float* gn_w   = (const float*)d_in[1];
    const float* gn_b   = (const float*)d_in[2];
    const float* qkv_w  = (const float*)d_in[3];
    const float* qkv_b  = (const float*)d_in[4];
    const float* proj_w = (const float*)d_in[5];
    const float* proj_b = (const float*)d_in[6];
    float* out = (float*)d_out;

    __half *xnh, *hh, *qh, *kh, *vh;
    cudaGetSymbolAddress((void**)&xnh, g_xnh);
    cudaGetSymbolAddress((void**)&hh,  g_hh);
    cudaGetSymbolAddress((void**)&qh,  g_qh);
    cudaGetSymbolAddress((void**)&kh,  g_kh);
    cudaGetSymbolAddress((void**)&vh,  g_vh);

    cudaFuncSetAttribute(gemm_qkv_h,
                         cudaFuncAttributeMaxDynamicSharedMemorySize, GEMM_SMEM);
    cudaFuncSetAttribute(gemm_proj_h,
                         cudaFuncAttributeMaxDynamicSharedMemorySize, GEMM_SMEM);
    cudaFuncSetAttribute(attn_mma_kernel,
                         cudaFuncAttributeMaxDynamicSharedMemorySize, ATT_SMEM);

    gn_stats_kernel<<<64, 256>>>(x, qkv_w, proj_w);
    gn_apply_t_kernel<<<dim3(4, 64, 2), 256>>>(x, gn_w, gn_b);
    gemm_qkv_h<<<dim3(32, 12, 2), 128, GEMM_SMEM>>>(xnh, qkv_b);
    attn_mma_kernel<<<dim3(32, 8, NSPLIT), 128, ATT_SMEM>>>(qh, kh, vh);
    attn_combine_kernel<<<2048, 256>>>();
    gemm_proj_h<<<dim3(32, 4, 2), 128, GEMM_SMEM>>>(hh, proj_b, x, out);
}